// round 17
// baseline (speedup 1.0000x reference)
#include <cuda_runtime.h>
#include <cuda_fp16.h>
#include <cstdint>

// Problem constants
#define M_DIM 4096
#define N_DIM 32000
#define KW 64            // K in half2 words
#define KP 68            // padded smem k-stride (words)
#define BM 128
#define BN 128
#define NT 8000          // total tiles (32 x 250)
#define A_BYTES (BM * KP * 4)        // 34,816
#define BUFB (2 * A_BYTES)           // 69,632 per buffer (A + B)
#define SMEM_BYTES (2 * BUFB)        // 139,264 -> 1 CTA/SM

// Device scratch
__device__ uint32_t g_Ah[M_DIM * KW];    // 1 MB fp16 A
__device__ uint32_t g_Wh[N_DIM * KW];    // 8.2 MB fp16 W
__device__ int g_stride;
__device__ unsigned g_ctr;               // persistent-tile counter

__device__ __forceinline__ uint32_t packh(float lo, float hi) {
    __half2 h = __floats2half2_rn(lo, hi);
    return *reinterpret_cast<uint32_t*>(&h);
}
__device__ __forceinline__ void cp16(uint32_t dst, const void* src) {
    asm volatile("cp.async.cg.shared.global [%0], [%1], 16;" :: "r"(dst), "l"(src));
}
template <int N> __device__ __forceinline__ void cp_wait() {
    asm volatile("cp.async.wait_group %0;" :: "n"(N));
}
__device__ __forceinline__ void ldsm4(unsigned& r0, unsigned& r1,
                                      unsigned& r2, unsigned& r3, uint32_t a) {
    asm volatile("ldmatrix.sync.aligned.m8n8.x4.shared.b16 {%0,%1,%2,%3}, [%4];"
                 : "=r"(r0), "=r"(r1), "=r"(r2), "=r"(r3) : "r"(a));
}

// ---------------------------------------------------------------------------
// Detect index dtype AND reset the persistent-tile counter (each launch).
// ---------------------------------------------------------------------------
__global__ void detect_kernel(const int* __restrict__ x32) {
    __shared__ int any;
    if (threadIdx.x == 0) { any = 0; g_ctr = 0u; }
    __syncthreads();
    int i = 1 + 2 * threadIdx.x;
    int v = x32[i] | x32[i + 512] | x32[i + 1024] | x32[i + 1536];
    if (v) any = 1;
    __syncthreads();
    if (threadIdx.x == 0) g_stride = any ? 1 : 2;
}

// ---------------------------------------------------------------------------
// W -> fp16 (packed half2).
// ---------------------------------------------------------------------------
__global__ void conv_w_kernel(const float4* __restrict__ W) {
    int i = blockIdx.x * 256 + threadIdx.x;   // 1,024,000 float4
    float4 v = W[i];
    g_Wh[i * 2]     = packh(v.x, v.y);
    g_Wh[i * 2 + 1] = packh(v.z, v.w);
}

// ---------------------------------------------------------------------------
// CBOW gather-sum (padding_idx=0 skipped), fp16 output.
// ---------------------------------------------------------------------------
__global__ void sum_emb_kernel(const int* __restrict__ x32,
                               const float4* __restrict__ emb) {
    int sample = blockIdx.x * 8 + (threadIdx.x >> 5);
    int v = threadIdx.x & 31;
    int stride = g_stride;
    float4 s = make_float4(0.f, 0.f, 0.f, 0.f);
#pragma unroll
    for (int c = 0; c < 8; c++) {
        int i = x32[(sample * 8 + c) * stride];
        if (i != 0) {
            float4 t = emb[i * 32 + v];
            s.x += t.x; s.y += t.y; s.z += t.z; s.w += t.w;
        }
    }
    int base = sample * KW + v * 2;
    g_Ah[base]     = packh(s.x, s.y);
    g_Ah[base + 1] = packh(s.z, s.w);
}

// ---------------------------------------------------------------------------
// Issue cp.async for one tile (A 32KB + B 32KB) into buffer `buf`; commit.
// 4096 cp16 / 512 threads = 8 each.
// ---------------------------------------------------------------------------
__device__ __forceinline__ void issue_tile(uint32_t sbase, int t, int buf,
                                           int tid) {
    const int bm = (t / 250) * BM;
    const int bn = (t % 250) * BN;
    const uint4* Ag = reinterpret_cast<const uint4*>(g_Ah) + bm * 16;
    const uint4* Bg = reinterpret_cast<const uint4*>(g_Wh) + bn * 16;
    const uint32_t base = sbase + buf * BUFB;
#pragma unroll
    for (int i = 0; i < 4; i++) {
        int idx = tid + i * 512;
        int row = idx >> 4, j = idx & 15;
        cp16(base + (row * KP + j * 4) * 4, Ag + row * 16 + j);
    }
#pragma unroll
    for (int i = 0; i < 4; i++) {
        int idx = tid + i * 512;
        int row = idx >> 4, j = idx & 15;
        cp16(base + A_BYTES + (row * KP + j * 4) * 4, Bg + row * 16 + j);
    }
    asm volatile("cp.async.commit_group;" ::: "memory");
}

// ---------------------------------------------------------------------------
// Persistent GEMM: out[M,N] = A[M,K] @ W[N,K]^T + b  (fp16 in, fp32 acc)
// grid 296 persistent CTAs (1/SM resident), 512 threads, 16 warps (4M x 4N),
// warp tile 32x32. Whole tiles double-buffered: tile t+1 streams via ONE
// cp.async group while tile t computes. Tiles from a global atomic counter
// (bn-fast order: concurrent CTAs share bm -> A L2-hot; W stays L2-resident).
// Kills per-CTA prologue latency x8000 and all wave transitions.
// ---------------------------------------------------------------------------
__global__ void __launch_bounds__(512, 1)
gemm_kernel(const float* __restrict__ bias, float* __restrict__ out) {
    extern __shared__ unsigned smem[];
    __shared__ unsigned s_t;
    const uint32_t sbase = (uint32_t)__cvta_generic_to_shared(smem);
    const int tid = threadIdx.x;

    auto grab = [&]() -> int {
        __syncthreads();
        if (tid == 0) s_t = atomicAdd(&g_ctr, 1u);
        __syncthreads();
        return (int)s_t;
    };

    int t_cur = grab();
    if (t_cur >= NT) return;
    issue_tile(sbase, t_cur, 0, tid);
    int t_next = grab();

    const int lane = tid & 31;
    const int warp = tid >> 5;
    const int wm = (warp & 3) * 32;    // 4 warps along M
    const int wn = (warp >> 2) * 32;   // 4 warps along N
    const int g  = lane >> 2;          // 0..7
    const int tg = lane & 3;           // 0..3
    const int t8 = lane >> 3, l8 = lane & 7;

    // ldmatrix base addresses for buffer 0 (R16-proven layouts)
    const uint32_t abase0 = sbase +
        ((wm + (t8 & 1) * 8 + l8) * KP + (t8 >> 1) * 4) * 4;
    const uint32_t bbase0 = sbase + A_BYTES +
        ((wn + (t8 >> 1) * 8 + l8) * KP + (t8 & 1) * 4) * 4;

    int p = 0;
    while (true) {
        if (t_next < NT) {
            issue_tile(sbase, t_next, p ^ 1, tid);
            cp_wait<1>();              // drain everything except t_next's group
        } else {
            cp_wait<0>();
        }
        __syncthreads();               // tile t_cur visible to all warps

        const uint32_t ab = abase0 + p * BUFB;
        const uint32_t bb2 = bbase0 + p * BUFB;

        float acc[2][4][4];
#pragma unroll
        for (int mi = 0; mi < 2; mi++)
#pragma unroll
            for (int ni = 0; ni < 4; ni++)
#pragma unroll
                for (int r = 0; r < 4; r++) acc[mi][ni][r] = 0.f;

#pragma unroll
        for (int ks = 0; ks < 8; ks++) {
            const uint32_t koff = ks * 32;     // 8 words * 4B
            unsigned a[2][4], b[2][4];
            ldsm4(a[0][0], a[0][1], a[0][2], a[0][3], ab + koff);
            ldsm4(a[1][0], a[1][1], a[1][2], a[1][3], ab + 16 * KP * 4 + koff);
            ldsm4(b[0][0], b[0][1], b[0][2], b[0][3], bb2 + koff);
            ldsm4(b[1][0], b[1][1], b[1][2], b[1][3], bb2 + 16 * KP * 4 + koff);
#pragma unroll
            for (int mi = 0; mi < 2; mi++)
#pragma unroll
                for (int ni = 0; ni < 4; ni++) {
                    const unsigned b0 = b[ni >> 1][(ni & 1) * 2];
                    const unsigned b1 = b[ni >> 1][(ni & 1) * 2 + 1];
                    asm volatile(
                        "mma.sync.aligned.m16n8k16.row.col.f32.f16.f16.f32 "
                        "{%0,%1,%2,%3}, {%4,%5,%6,%7}, {%8,%9}, {%0,%1,%2,%3};"
                        : "+f"(acc[mi][ni][0]), "+f"(acc[mi][ni][1]),
                          "+f"(acc[mi][ni][2]), "+f"(acc[mi][ni][3])
                        : "r"(a[mi][0]), "r"(a[mi][1]),
                          "r"(a[mi][2]), "r"(a[mi][3]),
                          "r"(b0), "r"(b1));
                }
        }

        // epilogue for t_cur (overlaps the in-flight next-tile cp.async)
        const int bm = (t_cur / 250) * BM;
        const int bn = (t_cur % 250) * BN;
#pragma unroll
        for (int ni = 0; ni < 4; ni++) {
            int col = bn + wn + ni * 8 + 2 * tg;
            float2 bb = *reinterpret_cast<const float2*>(bias + col);
#pragma unroll
            for (int mi = 0; mi < 2; mi++) {
                int row = bm + wm + mi * 16 + g;
                float2 v0 = make_float2(acc[mi][ni][0] + bb.x,
                                        acc[mi][ni][1] + bb.y);
                float2 v1 = make_float2(acc[mi][ni][2] + bb.x,
                                        acc[mi][ni][3] + bb.y);
                *reinterpret_cast<float2*>(out + (size_t)row * N_DIM + col) = v0;
                *reinterpret_cast<float2*>(out + (size_t)(row + 8) * N_DIM + col) = v1;
            }
        }

        if (t_next >= NT) break;
        t_cur = t_next;
        t_next = grab();               // its syncs also close buf-p reads
        p ^= 1;
    }
}

// ---------------------------------------------------------------------------
extern "C" void kernel_launch(void* const* d_in, const int* in_sizes, int n_in,
                              void* d_out, int out_size) {
    const int*   x    = (const int*)d_in[0];
    const float* emb  = (const float*)d_in[1];
    const float* W    = (const float*)d_in[2];
    const float* bias = (const float*)d_in[3];
    float* out = (float*)d_out;

    (void)in_sizes; (void)n_in; (void)out_size;

    cudaFuncSetAttribute(gemm_kernel,
                         cudaFuncAttributeMaxDynamicSharedMemorySize,
                         SMEM_BYTES);

    detect_kernel<<<1, 256>>>(x);
    conv_w_kernel<<<4000, 256>>>((const float4*)W);
    sum_emb_kernel<<<M_DIM / 8, 256>>>(x, (const float4*)emb);

    gemm_kernel<<<296, 512, SMEM_BYTES>>>(bias, out);
}